// round 16
// baseline (speedup 1.0000x reference)
#include <cuda_runtime.h>
#include <cstdint>

// CenterLoss collapses: mask is one-hot(labels) -> only B entries of the
// [B, C] distance matrix survive; clip() turns the other B*(C-1) zeros into
// the closed-form constant B*(C-1)*1e-12. No GEMM — 1 MB touched, not 410 MB.
//
// FINAL kernel. 128 blocks x 256 thr, one sample per warp.
//  - warp : redux.sync.add.u32 over 2^22 fixed-point lane partials
//           (1 HW instruction, exactly associative -> deterministic)
//  - block: lane0 stores the RAW u32 warp sum to smem, one bar.sync
//           (after loads/compute -> overlaps memory latency),
//           tid0 reads the 8 sums as TWO uint4 vector loads and does a
//           fixed-order u64 integer sum (1-cycle adds, exact)
//  - grid : ONE packed u64 atomicAdd:
//           bits [56,64): block count, bits [0,56): 2^22 fixed-point sum.
//           Integer adds are exactly associative -> bit-deterministic; the
//           block whose add completes the count RECEIVES the finished total
//           in the return value. It converts once, adds the exact clip
//           constant, writes out, and resets for the next graph replay.
// Clip(1e-12,1e12) never binds on real distances (~2*chi2(128) >> 1e-12);
// ranges: warp < 2^31, block < 2^34, total < 2^41 << 2^56.
//
// Measured history: kernel 5.60/5.66/5.60/5.50/5.60/5.47 us for the float
// combine, 5.41 us for the integer combine (R14). Rejected by measurement:
// 4-samples/warp @32 blocks (7.14), fence+counter tail (6.40), atomic tree
// (6.53), barrier-before-loads integer reduce (5.95). Residual = ~4.8 us
// harness launch/ramp floor + data-inherent labels->centers gather chain.

#define CL_BATCH 1024
#define CL_FEAT  128
#define CL_NUMC  100000

#define CL_THREADS 256
#define CL_BLOCKS  (CL_BATCH / 8)     // 128 blocks, 8 warps = 8 samples each

#define CL_LANE_SCALE 4194304.0f      // 2^22 (fixed point, whole pipeline)
#define CL_LANE_INV   (1.0 / 4194304.0)

#define CL_COUNT_UNIT (1ULL << 56)
#define CL_SUM_MASK  (CL_COUNT_UNIT - 1ULL)

// Exact closed-form contribution of the B*(C-1) clipped masked zeros.
constexpr double CL_CLIP_CONST =
    (double)CL_BATCH * (double)(CL_NUMC - 1) * 1e-12;

__device__ unsigned long long g_cl_accum = 0ULL;

__device__ __forceinline__ unsigned int warp_sum_u32(unsigned int v)
{
    // Hardware warp integer reduction (sm_80+): single instruction,
    // exactly associative -> deterministic.
    unsigned int r;
    asm volatile("redux.sync.add.u32 %0, %1, 0xffffffff;"
                 : "=r"(r) : "r"(v));
    return r;
}

__global__ void __launch_bounds__(CL_THREADS)
center_loss_fused(const float* __restrict__ x,
                  const int* __restrict__ labels,
                  const float* __restrict__ centers,
                  float* __restrict__ out)
{
    const int tid     = threadIdx.x;
    const int lane    = tid & 31;
    const int warpInB = tid >> 5;                      // 0..7
    const int sample  = blockIdx.x * 8 + warpInB;      // 0..1023

    // Broadcast label load (all lanes same address -> 1 request).
    const int lbl = labels[sample];

    // 128 floats per row = 32 lanes x float4; x-load is independent of the
    // label->center dependent chain and overlaps it.
    const float4 xv = reinterpret_cast<const float4*>(x + (size_t)sample * CL_FEAT)[lane];
    const float4 cv = reinterpret_cast<const float4*>(centers + (size_t)lbl * CL_FEAT)[lane];

    // ||x||^2 + ||c||^2 - 2 x.c, expanded like the reference.
    float p = 0.f;
    p += xv.x * xv.x + cv.x * cv.x - 2.f * xv.x * cv.x;
    p += xv.y * xv.y + cv.y * cv.y - 2.f * xv.y * cv.y;
    p += xv.z * xv.z + cv.z * cv.z - 2.f * xv.z * cv.z;
    p += xv.w * xv.w + cv.w * cv.w - 2.f * xv.w * cv.w;

    // 2^22 fixed point (rn; saturates tiny negative rounding to 0), then a
    // single-instruction exact warp sum. Result IS the quantized distance.
    const unsigned int usum = warp_sum_u32(__float2uint_rn(p * CL_LANE_SCALE));

    // Raw integer warp sum -> smem (16B-aligned array for vector reads).
    __shared__ __align__(16) unsigned int sm[8];
    if (lane == 0)
        sm[warpInB] = usum;
    __syncthreads();

    if (tid == 0) {
        // Two LDS.128 instead of eight LDS.32; fixed-order u64 sum, exact.
        const uint4 a = reinterpret_cast<const uint4*>(sm)[0];
        const uint4 b = reinterpret_cast<const uint4*>(sm)[1];
        unsigned long long bsum =
              (unsigned long long)a.x + (unsigned long long)a.y
            + (unsigned long long)a.z + (unsigned long long)a.w
            + (unsigned long long)b.x + (unsigned long long)b.y
            + (unsigned long long)b.z + (unsigned long long)b.w;

        const unsigned long long q = bsum + CL_COUNT_UNIT;
        const unsigned long long now = atomicAdd(&g_cl_accum, q) + q;

        if ((now >> 56) == (unsigned long long)CL_BLOCKS) {
            // This block completed the sum; 'now' holds the exact total.
            double total = (double)(now & CL_SUM_MASK) * CL_LANE_INV
                         + CL_CLIP_CONST;
            out[0] = (float)(total / (double)CL_BATCH);
            g_cl_accum = 0ULL;        // reset for next graph replay
        }
    }
}

extern "C" void kernel_launch(void* const* d_in, const int* in_sizes, int n_in,
                              void* d_out, int out_size)
{
    const float* x       = (const float*)d_in[0];
    const int*   labels  = (const int*)d_in[1];
    const float* centers = (const float*)d_in[2];
    float*       out     = (float*)d_out;

    center_loss_fused<<<CL_BLOCKS, CL_THREADS>>>(x, labels, centers, out);
}

// round 17
// speedup vs baseline: 1.0363x; 1.0363x over previous
#include <cuda_runtime.h>
#include <cstdint>

// CenterLoss collapses: mask is one-hot(labels) -> only B entries of the
// [B, C] distance matrix survive; clip() turns the other B*(C-1) zeros into
// the closed-form constant B*(C-1)*1e-12. No GEMM — 1 MB touched, not 410 MB.
//
// FINAL kernel (best measured: kernel 5.41 us, wall 6.18 us).
// 128 blocks x 256 thr, one sample per warp.
//  - warp : redux.sync.add.u32 over 2^22 fixed-point lane partials
//           (1 HW instruction, exactly associative -> deterministic)
//  - block: lane0 stores the RAW u32 warp sum to smem, one bar.sync
//           (after loads/compute -> overlaps memory latency),
//           tid0 does a fixed-order u64 integer sum of the 8 values
//  - grid : ONE packed u64 atomicAdd:
//           bits [56,64): block count, bits [0,56): 2^22 fixed-point sum.
//           Integer adds are exactly associative -> bit-deterministic; the
//           block whose add completes the count RECEIVES the finished total
//           in the return value. It converts once, adds the exact clip
//           constant, writes out, and resets for the next graph replay.
// Clip(1e-12,1e12) never binds on real distances (~2*chi2(128) >> 1e-12);
// ranges: warp < 2^31, block < 2^34, total < 2^41 << 2^56.
//
// Measured history (kernel us): float combine 5.47-5.66 over 6 benches;
// integer combine 5.41 (R14, best); uint4 tail 5.57 (R16, noise/regression).
// Rejected by measurement: 4-samples/warp @32 blocks (7.14), fence+counter
// tail (6.40), 3-level atomic tree (6.53), barrier-before-loads reduce
// (5.95). Residual = ~4.8 us harness launch/ramp floor + data-inherent
// labels->centers dependent gather chain. Nothing throughput-bound remains.

#define CL_BATCH 1024
#define CL_FEAT  128
#define CL_NUMC  100000

#define CL_THREADS 256
#define CL_BLOCKS  (CL_BATCH / 8)     // 128 blocks, 8 warps = 8 samples each

#define CL_LANE_SCALE 4194304.0f      // 2^22 (fixed point, whole pipeline)
#define CL_LANE_INV   (1.0 / 4194304.0)

#define CL_COUNT_UNIT (1ULL << 56)
#define CL_SUM_MASK  (CL_COUNT_UNIT - 1ULL)

// Exact closed-form contribution of the B*(C-1) clipped masked zeros.
constexpr double CL_CLIP_CONST =
    (double)CL_BATCH * (double)(CL_NUMC - 1) * 1e-12;

__device__ unsigned long long g_cl_accum = 0ULL;

__device__ __forceinline__ unsigned int warp_sum_u32(unsigned int v)
{
    // Hardware warp integer reduction (sm_80+): single instruction,
    // exactly associative -> deterministic.
    unsigned int r;
    asm volatile("redux.sync.add.u32 %0, %1, 0xffffffff;"
                 : "=r"(r) : "r"(v));
    return r;
}

__global__ void __launch_bounds__(CL_THREADS)
center_loss_fused(const float* __restrict__ x,
                  const int* __restrict__ labels,
                  const float* __restrict__ centers,
                  float* __restrict__ out)
{
    const int tid     = threadIdx.x;
    const int lane    = tid & 31;
    const int warpInB = tid >> 5;                      // 0..7
    const int sample  = blockIdx.x * 8 + warpInB;      // 0..1023

    // Broadcast label load (all lanes same address -> 1 request).
    const int lbl = labels[sample];

    // 128 floats per row = 32 lanes x float4; x-load is independent of the
    // label->center dependent chain and overlaps it.
    const float4 xv = reinterpret_cast<const float4*>(x + (size_t)sample * CL_FEAT)[lane];
    const float4 cv = reinterpret_cast<const float4*>(centers + (size_t)lbl * CL_FEAT)[lane];

    // ||x||^2 + ||c||^2 - 2 x.c, expanded like the reference.
    float p = 0.f;
    p += xv.x * xv.x + cv.x * cv.x - 2.f * xv.x * cv.x;
    p += xv.y * xv.y + cv.y * cv.y - 2.f * xv.y * cv.y;
    p += xv.z * xv.z + cv.z * cv.z - 2.f * xv.z * cv.z;
    p += xv.w * xv.w + cv.w * cv.w - 2.f * xv.w * cv.w;

    // 2^22 fixed point (rn; saturates tiny negative rounding to 0), then a
    // single-instruction exact warp sum. Result IS the quantized distance.
    const unsigned int usum = warp_sum_u32(__float2uint_rn(p * CL_LANE_SCALE));

    // Raw integer warp sum -> smem (no converts, no clip on the hot path).
    __shared__ unsigned int sm[8];
    if (lane == 0)
        sm[warpInB] = usum;
    __syncthreads();

    if (tid == 0) {
        // Fixed-order integer block sum: 8 one-cycle IADDs, exact.
        unsigned long long bsum = 0ULL;
        #pragma unroll
        for (int i = 0; i < 8; ++i) bsum += (unsigned long long)sm[i];

        const unsigned long long q = bsum + CL_COUNT_UNIT;
        const unsigned long long now = atomicAdd(&g_cl_accum, q) + q;

        if ((now >> 56) == (unsigned long long)CL_BLOCKS) {
            // This block completed the sum; 'now' holds the exact total.
            double total = (double)(now & CL_SUM_MASK) * CL_LANE_INV
                         + CL_CLIP_CONST;
            out[0] = (float)(total / (double)CL_BATCH);
            g_cl_accum = 0ULL;        // reset for next graph replay
        }
    }
}

extern "C" void kernel_launch(void* const* d_in, const int* in_sizes, int n_in,
                              void* d_out, int out_size)
{
    const float* x       = (const float*)d_in[0];
    const int*   labels  = (const int*)d_in[1];
    const float* centers = (const float*)d_in[2];
    float*       out     = (float*)d_out;

    center_loss_fused<<<CL_BLOCKS, CL_THREADS>>>(x, labels, centers, out);
}